// round 11
// baseline (speedup 1.0000x reference)
#include <cuda_runtime.h>

// Loss_31877247271387: BCE (torch log clamp at -100) + L2 reg + accuracy count.
// R3 measured: 33.5us @ DRAM 60%, occ 45% (32 warps/SM) -> latency bound.
// This candidate: (1) occupancy 6 CTAs/SM (<=42 regs: BCE batch 2-deep,
// W batches 4-deep), grid 888 = 148*6 single wave; (2) blocks proportional
// to BYTES streamed: BCE reads 134MB (2 streams) -> 548 blocks, w1 67MB ->
// 272, w2 16.8MB -> 68; ~246 KB/block everywhere so all sections finish
// together at DRAM-bound steady state.

#define TPB     256
#define NB_BCE  548
#define NB_W1   272
#define NB_W2   68
#define NB_TOTAL (NB_BCE + NB_W1 + NB_W2)

__device__ float g_bce_part[NB_BCE];
__device__ float g_cnt_part[NB_BCE];
__device__ float g_w1_part[NB_W1];
__device__ float g_w2_part[NB_W2];
__device__ unsigned int g_retire = 0;

__device__ __forceinline__ float bce_term(float p, float y)
{
    // y*log(p) + (1-y)*log(1-p) == l1p + y*(lp - l1p), torch clamp at -100.
    float lp  = fmaxf(__logf(p),        -100.0f);
    float l1p = fmaxf(__logf(1.0f - p), -100.0f);
    return fmaf(y, lp - l1p, l1p);
}

__device__ __forceinline__ float sq4(float4 v, float acc)
{
    acc = fmaf(v.x, v.x, acc);
    acc = fmaf(v.y, v.y, acc);
    acc = fmaf(v.z, v.z, acc);
    acc = fmaf(v.w, v.w, acc);
    return acc;
}

__device__ __forceinline__ float warp_sum(float v)
{
    v += __shfl_xor_sync(0xFFFFFFFFu, v, 16);
    v += __shfl_xor_sync(0xFFFFFFFFu, v, 8);
    v += __shfl_xor_sync(0xFFFFFFFFu, v, 4);
    v += __shfl_xor_sync(0xFFFFFFFFu, v, 2);
    v += __shfl_xor_sync(0xFFFFFFFFu, v, 1);
    return v;
}

// Block sum; result valid in thread 0.
__device__ __forceinline__ float block_sum(float v, float* scratch)
{
    const int lane = threadIdx.x & 31;
    const int wid  = threadIdx.x >> 5;
    v = warp_sum(v);
    if (lane == 0) scratch[wid] = v;
    __syncthreads();
    float r = 0.0f;
    if (wid == 0) {
        float x = (lane < TPB / 32) ? scratch[lane] : 0.0f;
        r = warp_sum(x);
    }
    __syncthreads();
    return r;
}

__global__ __launch_bounds__(TPB, 6)
void loss_kernel(const float4* __restrict__ mo,
                 const float4* __restrict__ lb, int n4_bce,
                 const float4* __restrict__ w1, int n4_w1,
                 const float4* __restrict__ w2, int n4_w2,
                 float* __restrict__ out, int out_size, float batch_size)
{
    const int b = blockIdx.x;
    const int t = threadIdx.x;
    __shared__ float scr[TPB / 32];
    __shared__ bool  is_last;

    if (b < NB_BCE) {
        // ---- BCE + accuracy count: 2-deep batch (4 in-flight LDG.128) ----
        float a0 = 0.0f, a1 = 0.0f, c0 = 0.0f;
        const int stride = NB_BCE * TPB;
        int i = b * TPB + t;
        for (; i + stride < n4_bce; i += 2 * stride) {
            float4 p0 = __ldg(&mo[i]);
            float4 p1 = __ldg(&mo[i + stride]);
            float4 y0 = __ldg(&lb[i]);
            float4 y1 = __ldg(&lb[i + stride]);
            a0 += bce_term(p0.x, y0.x) + bce_term(p0.y, y0.y)
                + bce_term(p0.z, y0.z) + bce_term(p0.w, y0.w);
            a1 += bce_term(p1.x, y1.x) + bce_term(p1.y, y1.y)
                + bce_term(p1.z, y1.z) + bce_term(p1.w, y1.w);
            c0 += ((fabsf(p0.x - y0.x) < 0.5f) ? 1.0f : 0.0f)
                + ((fabsf(p0.y - y0.y) < 0.5f) ? 1.0f : 0.0f)
                + ((fabsf(p0.z - y0.z) < 0.5f) ? 1.0f : 0.0f)
                + ((fabsf(p0.w - y0.w) < 0.5f) ? 1.0f : 0.0f)
                + ((fabsf(p1.x - y1.x) < 0.5f) ? 1.0f : 0.0f)
                + ((fabsf(p1.y - y1.y) < 0.5f) ? 1.0f : 0.0f)
                + ((fabsf(p1.z - y1.z) < 0.5f) ? 1.0f : 0.0f)
                + ((fabsf(p1.w - y1.w) < 0.5f) ? 1.0f : 0.0f);
        }
        for (; i < n4_bce; i += stride) {
            float4 p = __ldg(&mo[i]);
            float4 y = __ldg(&lb[i]);
            a0 += bce_term(p.x, y.x) + bce_term(p.y, y.y)
                + bce_term(p.z, y.z) + bce_term(p.w, y.w);
            c0 += ((fabsf(p.x - y.x) < 0.5f) ? 1.0f : 0.0f)
                + ((fabsf(p.y - y.y) < 0.5f) ? 1.0f : 0.0f)
                + ((fabsf(p.z - y.z) < 0.5f) ? 1.0f : 0.0f)
                + ((fabsf(p.w - y.w) < 0.5f) ? 1.0f : 0.0f);
        }
        float ba = block_sum(a0 + a1, scr);
        float bc = block_sum(c0, scr);
        if (t == 0) {
            g_bce_part[b] = ba;
            g_cnt_part[b] = bc;
        }
    } else if (b < NB_BCE + NB_W1) {
        // ---- sum(w1*w1): 4-deep batch ----
        const int bb = b - NB_BCE;
        float a0 = 0.0f, a1 = 0.0f, a2 = 0.0f, a3 = 0.0f;
        const int stride = NB_W1 * TPB;
        int i = bb * TPB + t;
        for (; i + 3 * stride < n4_w1; i += 4 * stride) {
            float4 v0 = __ldg(&w1[i]);
            float4 v1 = __ldg(&w1[i + stride]);
            float4 v2 = __ldg(&w1[i + 2 * stride]);
            float4 v3 = __ldg(&w1[i + 3 * stride]);
            a0 = sq4(v0, a0); a1 = sq4(v1, a1);
            a2 = sq4(v2, a2); a3 = sq4(v3, a3);
        }
        for (; i < n4_w1; i += stride) a0 = sq4(__ldg(&w1[i]), a0);
        float ba = block_sum((a0 + a1) + (a2 + a3), scr);
        if (t == 0) g_w1_part[bb] = ba;
    } else {
        // ---- sum(w2*w2): 4-deep batch ----
        const int bb = b - NB_BCE - NB_W1;
        float a0 = 0.0f, a1 = 0.0f, a2 = 0.0f, a3 = 0.0f;
        const int stride = NB_W2 * TPB;
        int i = bb * TPB + t;
        for (; i + 3 * stride < n4_w2; i += 4 * stride) {
            float4 v0 = __ldg(&w2[i]);
            float4 v1 = __ldg(&w2[i + stride]);
            float4 v2 = __ldg(&w2[i + 2 * stride]);
            float4 v3 = __ldg(&w2[i + 3 * stride]);
            a0 = sq4(v0, a0); a1 = sq4(v1, a1);
            a2 = sq4(v2, a2); a3 = sq4(v3, a3);
        }
        for (; i < n4_w2; i += stride) a0 = sq4(__ldg(&w2[i]), a0);
        float ba = block_sum((a0 + a1) + (a2 + a3), scr);
        if (t == 0) g_w2_part[bb] = ba;
    }

    // ---- last-block combine (self-resetting => graph-replay deterministic) ----
    if (t == 0) {
        __threadfence();
        unsigned int ticket = atomicAdd(&g_retire, 1u);
        is_last = (ticket == (unsigned int)(NB_TOTAL - 1));
    }
    __syncthreads();

    if (is_last) {
        __shared__ double sb[TPB], sc2[TPB], sw1[TPB], sw2[TPB];
        double ab = 0.0, ac = 0.0, aw1 = 0.0, aw2 = 0.0;
        for (int i = t; i < NB_BCE; i += TPB) {
            ab += (double)__ldcg(&g_bce_part[i]);
            ac += (double)__ldcg(&g_cnt_part[i]);
        }
        for (int i = t; i < NB_W1; i += TPB) aw1 += (double)__ldcg(&g_w1_part[i]);
        for (int i = t; i < NB_W2; i += TPB) aw2 += (double)__ldcg(&g_w2_part[i]);

        sb[t] = ab; sc2[t] = ac; sw1[t] = aw1; sw2[t] = aw2;
        __syncthreads();
        for (int off = TPB / 2; off > 0; off >>= 1) {
            if (t < off) {
                sb[t]  += sb[t + off];
                sc2[t] += sc2[t + off];
                sw1[t] += sw1[t + off];
                sw2[t] += sw2[t + off];
            }
            __syncthreads();
        }
        if (t == 0) {
            double B = (double)batch_size;
            double cross = -sb[0] / B;
            double reg = 0.01 * sw1[0] / (2.0 * B) + 0.001 * sw2[0] / (2.0 * B);
            out[0] = (float)(cross + reg);
            if (out_size > 1) out[1] = (float)sc2[0];
            g_retire = 0;
        }
    }
}

extern "C" void kernel_launch(void* const* d_in, const int* in_sizes, int n_in,
                              void* d_out, int out_size)
{
    const float4* mo = (const float4*)d_in[0];
    const float4* lb = (const float4*)d_in[1];
    const float4* w1 = (const float4*)d_in[2];
    const float4* w2 = (const float4*)d_in[3];

    const int n_bce = in_sizes[0];
    const int n_w1  = in_sizes[2];
    const int n_w2  = in_sizes[3];

    loss_kernel<<<NB_TOTAL, TPB>>>(mo, lb, n_bce / 4,
                                   w1, n_w1 / 4,
                                   w2, n_w2 / 4,
                                   (float*)d_out, out_size, (float)n_bce);
}

// round 17
// speedup vs baseline: 1.0385x; 1.0385x over previous
#include <cuda_runtime.h>

// Loss_31877247271387: BCE (torch log clamp at -100) + L2 reg + accuracy count.
// R3: 32.6us kernel @ occ 45%, DRAM 60%, balanced blocks (254KB/blk).
// R11: 32.9us kernel @ occ 63%, DRAM 59.5% -- blocks MISbalanced (W blocks
//   carried 2x bytes -> 42MB W-tail on 38% of warps; time-weighted DRAM ~60%
//   is consistent with phase-1 at ~75%, so R11 does NOT falsify occupancy).
// This kernel (discriminating experiment, dominant vs best-known): occ-6 +
// CORRECT balance: BCE 67MB/396 = 169KB/blk, w1 67MB/392 = 171KB/blk,
// w2 16.8MB/100 = 168KB/blk. Grid 888 = 148*6 single wave, regs ~40.
// Hypothesis A (occ is the lever): dur -> 25-28us, DRAM 72-80%.
// Hypothesis B (~4.7TB/s achieved-BW ceiling): dur flat ~32us -> accept floor.

#define TPB     256
#define NB_BCE  396
#define NB_W1   392
#define NB_W2   100
#define NB_TOTAL (NB_BCE + NB_W1 + NB_W2)

__device__ float g_bce_part[NB_BCE];
__device__ float g_cnt_part[NB_BCE];
__device__ float g_w1_part[NB_W1];
__device__ float g_w2_part[NB_W2];
__device__ unsigned int g_retire = 0;

__device__ __forceinline__ float bce_term(float p, float y)
{
    // y*log(p) + (1-y)*log(1-p) == l1p + y*(lp - l1p), torch clamp at -100.
    float lp  = fmaxf(__logf(p),        -100.0f);
    float l1p = fmaxf(__logf(1.0f - p), -100.0f);
    return fmaf(y, lp - l1p, l1p);
}

__device__ __forceinline__ float sq4(float4 v, float acc)
{
    acc = fmaf(v.x, v.x, acc);
    acc = fmaf(v.y, v.y, acc);
    acc = fmaf(v.z, v.z, acc);
    acc = fmaf(v.w, v.w, acc);
    return acc;
}

__device__ __forceinline__ float warp_sum(float v)
{
    v += __shfl_xor_sync(0xFFFFFFFFu, v, 16);
    v += __shfl_xor_sync(0xFFFFFFFFu, v, 8);
    v += __shfl_xor_sync(0xFFFFFFFFu, v, 4);
    v += __shfl_xor_sync(0xFFFFFFFFu, v, 2);
    v += __shfl_xor_sync(0xFFFFFFFFu, v, 1);
    return v;
}

// Block sum; result valid in thread 0.
__device__ __forceinline__ float block_sum(float v, float* scratch)
{
    const int lane = threadIdx.x & 31;
    const int wid  = threadIdx.x >> 5;
    v = warp_sum(v);
    if (lane == 0) scratch[wid] = v;
    __syncthreads();
    float r = 0.0f;
    if (wid == 0) {
        float x = (lane < TPB / 32) ? scratch[lane] : 0.0f;
        r = warp_sum(x);
    }
    __syncthreads();
    return r;
}

__global__ __launch_bounds__(TPB, 6)
void loss_kernel(const float4* __restrict__ mo,
                 const float4* __restrict__ lb, int n4_bce,
                 const float4* __restrict__ w1, int n4_w1,
                 const float4* __restrict__ w2, int n4_w2,
                 float* __restrict__ out, int out_size, float batch_size)
{
    const int b = blockIdx.x;
    const int t = threadIdx.x;
    __shared__ float scr[TPB / 32];
    __shared__ bool  is_last;

    if (b < NB_BCE) {
        // ---- BCE + accuracy count: 2-deep batch (4 in-flight LDG.128) ----
        float a0 = 0.0f, a1 = 0.0f, c0 = 0.0f;
        const int stride = NB_BCE * TPB;
        int i = b * TPB + t;
        for (; i + stride < n4_bce; i += 2 * stride) {
            float4 p0 = __ldg(&mo[i]);
            float4 p1 = __ldg(&mo[i + stride]);
            float4 y0 = __ldg(&lb[i]);
            float4 y1 = __ldg(&lb[i + stride]);
            a0 += bce_term(p0.x, y0.x) + bce_term(p0.y, y0.y)
                + bce_term(p0.z, y0.z) + bce_term(p0.w, y0.w);
            a1 += bce_term(p1.x, y1.x) + bce_term(p1.y, y1.y)
                + bce_term(p1.z, y1.z) + bce_term(p1.w, y1.w);
            c0 += ((fabsf(p0.x - y0.x) < 0.5f) ? 1.0f : 0.0f)
                + ((fabsf(p0.y - y0.y) < 0.5f) ? 1.0f : 0.0f)
                + ((fabsf(p0.z - y0.z) < 0.5f) ? 1.0f : 0.0f)
                + ((fabsf(p0.w - y0.w) < 0.5f) ? 1.0f : 0.0f)
                + ((fabsf(p1.x - y1.x) < 0.5f) ? 1.0f : 0.0f)
                + ((fabsf(p1.y - y1.y) < 0.5f) ? 1.0f : 0.0f)
                + ((fabsf(p1.z - y1.z) < 0.5f) ? 1.0f : 0.0f)
                + ((fabsf(p1.w - y1.w) < 0.5f) ? 1.0f : 0.0f);
        }
        for (; i < n4_bce; i += stride) {
            float4 p = __ldg(&mo[i]);
            float4 y = __ldg(&lb[i]);
            a0 += bce_term(p.x, y.x) + bce_term(p.y, y.y)
                + bce_term(p.z, y.z) + bce_term(p.w, y.w);
            c0 += ((fabsf(p.x - y.x) < 0.5f) ? 1.0f : 0.0f)
                + ((fabsf(p.y - y.y) < 0.5f) ? 1.0f : 0.0f)
                + ((fabsf(p.z - y.z) < 0.5f) ? 1.0f : 0.0f)
                + ((fabsf(p.w - y.w) < 0.5f) ? 1.0f : 0.0f);
        }
        float ba = block_sum(a0 + a1, scr);
        float bc = block_sum(c0, scr);
        if (t == 0) {
            g_bce_part[b] = ba;
            g_cnt_part[b] = bc;
        }
    } else if (b < NB_BCE + NB_W1) {
        // ---- sum(w1*w1): 4-deep batch ----
        const int bb = b - NB_BCE;
        float a0 = 0.0f, a1 = 0.0f, a2 = 0.0f, a3 = 0.0f;
        const int stride = NB_W1 * TPB;
        int i = bb * TPB + t;
        for (; i + 3 * stride < n4_w1; i += 4 * stride) {
            float4 v0 = __ldg(&w1[i]);
            float4 v1 = __ldg(&w1[i + stride]);
            float4 v2 = __ldg(&w1[i + 2 * stride]);
            float4 v3 = __ldg(&w1[i + 3 * stride]);
            a0 = sq4(v0, a0); a1 = sq4(v1, a1);
            a2 = sq4(v2, a2); a3 = sq4(v3, a3);
        }
        for (; i < n4_w1; i += stride) a0 = sq4(__ldg(&w1[i]), a0);
        float ba = block_sum((a0 + a1) + (a2 + a3), scr);
        if (t == 0) g_w1_part[bb] = ba;
    } else {
        // ---- sum(w2*w2): 4-deep batch ----
        const int bb = b - NB_BCE - NB_W1;
        float a0 = 0.0f, a1 = 0.0f, a2 = 0.0f, a3 = 0.0f;
        const int stride = NB_W2 * TPB;
        int i = bb * TPB + t;
        for (; i + 3 * stride < n4_w2; i += 4 * stride) {
            float4 v0 = __ldg(&w2[i]);
            float4 v1 = __ldg(&w2[i + stride]);
            float4 v2 = __ldg(&w2[i + 2 * stride]);
            float4 v3 = __ldg(&w2[i + 3 * stride]);
            a0 = sq4(v0, a0); a1 = sq4(v1, a1);
            a2 = sq4(v2, a2); a3 = sq4(v3, a3);
        }
        for (; i < n4_w2; i += stride) a0 = sq4(__ldg(&w2[i]), a0);
        float ba = block_sum((a0 + a1) + (a2 + a3), scr);
        if (t == 0) g_w2_part[bb] = ba;
    }

    // ---- last-block combine (self-resetting => graph-replay deterministic) ----
    if (t == 0) {
        __threadfence();
        unsigned int ticket = atomicAdd(&g_retire, 1u);
        is_last = (ticket == (unsigned int)(NB_TOTAL - 1));
    }
    __syncthreads();

    if (is_last) {
        __shared__ double sb[TPB], sc2[TPB], sw1[TPB], sw2[TPB];
        double ab = 0.0, ac = 0.0, aw1 = 0.0, aw2 = 0.0;
        for (int i = t; i < NB_BCE; i += TPB) {
            ab += (double)__ldcg(&g_bce_part[i]);
            ac += (double)__ldcg(&g_cnt_part[i]);
        }
        for (int i = t; i < NB_W1; i += TPB) aw1 += (double)__ldcg(&g_w1_part[i]);
        for (int i = t; i < NB_W2; i += TPB) aw2 += (double)__ldcg(&g_w2_part[i]);

        sb[t] = ab; sc2[t] = ac; sw1[t] = aw1; sw2[t] = aw2;
        __syncthreads();
        for (int off = TPB / 2; off > 0; off >>= 1) {
            if (t < off) {
                sb[t]  += sb[t + off];
                sc2[t] += sc2[t + off];
                sw1[t] += sw1[t + off];
                sw2[t] += sw2[t + off];
            }
            __syncthreads();
        }
        if (t == 0) {
            double B = (double)batch_size;
            double cross = -sb[0] / B;
            double reg = 0.01 * sw1[0] / (2.0 * B) + 0.001 * sw2[0] / (2.0 * B);
            out[0] = (float)(cross + reg);
            if (out_size > 1) out[1] = (float)sc2[0];
            g_retire = 0;
        }
    }
}

extern "C" void kernel_launch(void* const* d_in, const int* in_sizes, int n_in,
                              void* d_out, int out_size)
{
    const float4* mo = (const float4*)d_in[0];
    const float4* lb = (const float4*)d_in[1];
    const float4* w1 = (const float4*)d_in[2];
    const float4* w2 = (const float4*)d_in[3];

    const int n_bce = in_sizes[0];
    const int n_w1  = in_sizes[2];
    const int n_w2  = in_sizes[3];

    loss_kernel<<<NB_TOTAL, TPB>>>(mo, lb, n_bce / 4,
                                   w1, n_w1 / 4,
                                   w2, n_w2 / 4,
                                   (float*)d_out, out_size, (float)n_bce);
}